// round 13
// baseline (speedup 1.0000x reference)
#include <cuda_runtime.h>
#include <cuda_bf16.h>
#include <cstdint>

// ============================================================================
// ContrastiveLoss via mma.sync bf16 m16n8k16 + ldmatrix + cp.async.
// Round 13: unbundle R12. Separate GEMM launches (R11 shape — fusion suspected
// cause of the R12 regression), KEEP depth-2 prefetch on the 3-stage ring,
// merge the 4 cvt pre-passes into one kernel.
// scores[b,c] = sum_r max_{w<cl[c]} <A[b,r,:], S[c,w,:]> / (obj[b]+1e-6)
// ============================================================================

namespace {
constexpr int D = 1024;
constexpr int BM = 128;
constexpr int BK = 32;                  // k elems per chunk (2 x k16 steps)
constexpr int NCHUNK = D / BK;          // 32
constexpr int SROW = 40;                // bf16 elems per smem row (80 B)
constexpr int STAGE_BYTES = BM * SROW * 2;   // 10240
constexpr int SMEM_DYN = 6 * STAGE_BYTES;    // 61440 (A:0..2, B:3..5)
constexpr int BSZ_C = 128;
constexpr int R1 = 36, W1 = 50;
constexpr int R2 = 25, W2 = 30;
constexpr int M1 = BSZ_C * R1;          // 4608
constexpr int M2 = BSZ_C * R2;          // 3200
// cvt segment sizes in float4 units
constexpr int NA1 = M1 * D / 4;             // 1179648
constexpr int NB1 = BSZ_C * W1 * D / 4;     // 1638400
constexpr int NA2 = M2 * D / 4;             // 819200
constexpr int NB2 = BSZ_C * W2 * D / 4;     // 983040
constexpr int NCVT = NA1 + NB1 + NA2 + NB2; // 4620288
}

// bf16 scratch (separate per part)
__device__ __nv_bfloat16 g_A1[M1 * D];
__device__ __nv_bfloat16 g_B1[BSZ_C * W1 * D];
__device__ __nv_bfloat16 g_A2[M2 * D];
__device__ __nv_bfloat16 g_B2[BSZ_C * W2 * D];
__device__ float g_scores[BSZ_C * BSZ_C];
__device__ float g_loss;

__global__ void zero_kernel(int n) {
    int i = blockIdx.x * blockDim.x + threadIdx.x;
    if (i < n) g_scores[i] = 0.0f;
    if (i == 0) g_loss = 0.0f;
}

__device__ __forceinline__ uint32_t smem_u32(const void* p) {
    uint32_t a;
    asm("{ .reg .u64 t; cvta.to.shared.u64 t, %1; cvt.u32.u64 %0, t; }" : "=r"(a) : "l"(p));
    return a;
}
__device__ __forceinline__ uint32_t pack_bf16(float lo, float hi) {
    __nv_bfloat162 h = __floats2bfloat162_rn(lo, hi);
    return *reinterpret_cast<uint32_t*>(&h);
}
__device__ __forceinline__ void ldsm_x4(uint32_t addr, uint32_t* r) {
    asm volatile("ldmatrix.sync.aligned.m8n8.x4.shared.b16 {%0,%1,%2,%3}, [%4];"
                 : "=r"(r[0]), "=r"(r[1]), "=r"(r[2]), "=r"(r[3]) : "r"(addr));
}
__device__ __forceinline__ void ldsm_x2(uint32_t addr, uint32_t* r) {
    asm volatile("ldmatrix.sync.aligned.m8n8.x2.shared.b16 {%0,%1}, [%2];"
                 : "=r"(r[0]), "=r"(r[1]) : "r"(addr));
}
__device__ __forceinline__ void mma_bf16(float* c, const uint32_t* a, const uint32_t* b) {
    asm volatile(
        "mma.sync.aligned.m16n8k16.row.col.f32.bf16.bf16.f32 "
        "{%0,%1,%2,%3}, {%4,%5,%6,%7}, {%8,%9}, {%0,%1,%2,%3};"
        : "+f"(c[0]), "+f"(c[1]), "+f"(c[2]), "+f"(c[3])
        : "r"(a[0]), "r"(a[1]), "r"(a[2]), "r"(a[3]), "r"(b[0]), "r"(b[1]));
}
__device__ __forceinline__ void cp16(uint32_t dst, const void* src) {
    asm volatile("cp.async.cg.shared.global [%0], [%1], 16;" :: "r"(dst), "l"(src));
}

// single fp32->bf16 pre-pass covering all four tensors
__global__ void cvt_all_kernel(const float* __restrict__ im, const float* __restrict__ s,
                               const float* __restrict__ pred, const float* __restrict__ sp) {
    int i = blockIdx.x * blockDim.x + threadIdx.x;
    const float* src;
    __nv_bfloat16* dst;
    int j = i;
    if (j < NA1)                { src = im;   dst = g_A1; }
    else if ((j -= NA1) < NB1)  { src = s;    dst = g_B1; }
    else if ((j -= NB1) < NA2)  { src = pred; dst = g_A2; }
    else if ((j -= NA2) < NB2)  { src = sp;   dst = g_B2; }
    else return;
    float4 v = ((const float4*)src)[j];
    ((uint2*)dst)[j] = make_uint2(pack_bf16(v.x, v.y), pack_bf16(v.z, v.w));
}

// A: bf16 [Bsz*R, D]; Bm: bf16 [Bsz, W, D].
template <int NT, int WPAD>
__global__ void __launch_bounds__(256, 2)
xattn_cp_kernel(const __nv_bfloat16* __restrict__ A, const __nv_bfloat16* __restrict__ Bm,
                const int* __restrict__ cap_lens, const int* __restrict__ obj_nums,
                int R, int W, int Bsz)
{
    constexpr int BNW = NT * 8;              // cols per warp (56 or 64)
    constexpr int BN  = 2 * BNW;             // cols per CTA (112 or 128)
    constexpr int CPW = BNW / WPAD;          // captions per warp (1 or 2)
    constexpr int CAPS_PER_TILE = 2 * CPW;
    constexpr int NB4 = NT / 2;
    constexpr bool HASX2 = (NT & 1) != 0;

    extern __shared__ __align__(16) unsigned char smraw[];   // [6][STAGE_BYTES]
    const uint32_t sbase = smem_u32(smraw);

    const int tid  = threadIdx.x;
    const int wid  = tid >> 5;
    const int lane = tid & 31;
    const int g = lane >> 2;
    const int t = lane & 3;
    const int wm = wid & 3;
    const int wn = wid >> 2;
    const int m0 = blockIdx.x * BM;
    const int cbase = blockIdx.y * CAPS_PER_TILE;

    // ---- cp.async slot mapping
    const __nv_bfloat16* srcA[2];
    const __nv_bfloat16* srcB[2];
    bool bval[2];
    uint32_t dstOff[2];
#pragma unroll
    for (int i = 0; i < 2; i++) {
        const int slot = tid + i * 256;
        const int row  = slot >> 2;
        const int c16  = slot & 3;
        dstOff[i] = (uint32_t)(row * (SROW * 2) + c16 * 16);
        srcA[i] = A + (size_t)(m0 + row) * D + c16 * 8;
        const int cap  = row / WPAD;
        const int word = row - cap * WPAD;
        bval[i] = (row < BN) && (word < W);
        const int capc = (cap < CAPS_PER_TILE) ? cap : 0;
        srcB[i] = Bm + ((size_t)(cbase + capc) * W + word) * D + c16 * 8;
    }

    // zero B-stage rows cp.async never writes
    {
        const uint4 z = make_uint4(0u, 0u, 0u, 0u);
        for (int idx = tid; idx < 128 * 5; idx += 256) {
            const int row = idx / 5;
            const int c   = idx - row * 5;
            const int cap  = row / WPAD;
            const int word = row - cap * WPAD;
            const bool valid = (row < BN) && (word < W);
            if (!valid) {
#pragma unroll
                for (int s = 0; s < 3; s++)
                    *(uint4*)(smraw + (3 + s) * STAGE_BYTES + row * (SROW * 2) + c * 16) = z;
            }
        }
    }

    float acc[2][NT][4];
#pragma unroll
    for (int mt = 0; mt < 2; mt++)
#pragma unroll
        for (int nt = 0; nt < NT; nt++)
#pragma unroll
            for (int e = 0; e < 4; e++) acc[mt][nt][e] = 0.0f;

    uint32_t aoff[2];
#pragma unroll
    for (int mt = 0; mt < 2; mt++)
        aoff[mt] = (uint32_t)((wm * 32 + mt * 16 + (lane & 15)) * (SROW * 2) + ((lane >> 4) << 4));
    uint32_t boff[NB4 + (HASX2 ? 1 : 0)];
#pragma unroll
    for (int nb = 0; nb < NB4; nb++) {
        const int n_local = (lane & 7) + ((lane & 16) ? 8 : 0);
        const int kb = (lane & 8) ? 16 : 0;
        boff[nb] = (uint32_t)((wn * BNW + nb * 16 + n_local) * (SROW * 2) + kb);
    }
    if (HASX2) {
        const int n_local = lane & 7;
        const int kb = (lane & 8) ? 16 : 0;
        boff[NB4] = (uint32_t)((wn * BNW + NB4 * 16 + n_local) * (SROW * 2) + kb);
    }

    auto issue = [&](int ch) {
        const int s = ch % 3;
        const int off = ch * BK;
#pragma unroll
        for (int i = 0; i < 2; i++)
            cp16(sbase + s * STAGE_BYTES + dstOff[i], srcA[i] + off);
#pragma unroll
        for (int i = 0; i < 2; i++)
            if (bval[i])
                cp16(sbase + (3 + s) * STAGE_BYTES + dstOff[i], srcB[i] + off);
        asm volatile("cp.async.commit_group;" ::: "memory");
    };

    auto compute = [&](int s) {
        const uint32_t abase = sbase + s * STAGE_BYTES;
        const uint32_t bbase = sbase + (3 + s) * STAGE_BYTES;
#pragma unroll
        for (int ks = 0; ks < 2; ks++) {
            const uint32_t ko = ks * 32;
            uint32_t afr[2][4];
#pragma unroll
            for (int mt = 0; mt < 2; mt++) ldsm_x4(abase + aoff[mt] + ko, afr[mt]);
            uint32_t bfr[NB4 + (HASX2 ? 1 : 0)][4];
#pragma unroll
            for (int nb = 0; nb < NB4; nb++) ldsm_x4(bbase + boff[nb] + ko, bfr[nb]);
            if (HASX2) ldsm_x2(bbase + boff[NB4] + ko, bfr[NB4]);
#pragma unroll
            for (int mt = 0; mt < 2; mt++)
#pragma unroll
                for (int nt = 0; nt < NT; nt++)
                    mma_bf16(acc[mt][nt], afr[mt], &bfr[nt >> 1][(nt & 1) * 2]);
        }
    };

    // depth-2 prefetch on the 3-stage ring
    issue(0);
    issue(1);

    for (int ch = 0; ch < NCHUNK; ch++) {
        if (ch + 1 < NCHUNK) {
            asm volatile("cp.async.wait_group 1;" ::: "memory");   // stage ch ready
        } else {
            asm volatile("cp.async.wait_group 0;" ::: "memory");
        }
        __syncthreads();                    // all warps done with stage (ch-1)%3
        if (ch + 2 < NCHUNK) issue(ch + 2); // writes stage (ch-1)%3 — now free
        compute(ch % 3);
    }

    // ---- epilogue
    int clv[CPW];
#pragma unroll
    for (int cap = 0; cap < CPW; cap++)
        clv[cap] = cap_lens[cbase + wn * CPW + cap];

    float mx[2][2][CPW];
#pragma unroll
    for (int mt = 0; mt < 2; mt++)
#pragma unroll
        for (int h = 0; h < 2; h++)
#pragma unroll
            for (int cap = 0; cap < CPW; cap++)
                mx[mt][h][cap] = -1e30f;

#pragma unroll
    for (int mt = 0; mt < 2; mt++)
#pragma unroll
        for (int nt = 0; nt < NT; nt++)
#pragma unroll
            for (int e = 0; e < 2; e++) {
                const int wc = nt * 8 + 2 * t + e;
                const int cap  = wc / WPAD;
                const int wpos = wc - cap * WPAD;
                if (wpos < clv[cap]) {
                    mx[mt][0][cap] = fmaxf(mx[mt][0][cap], acc[mt][nt][e]);
                    mx[mt][1][cap] = fmaxf(mx[mt][1][cap], acc[mt][nt][2 + e]);
                }
            }

#pragma unroll
    for (int mt = 0; mt < 2; mt++)
#pragma unroll
        for (int h = 0; h < 2; h++)
#pragma unroll
            for (int cap = 0; cap < CPW; cap++) {
                float v = mx[mt][h][cap];
                v = fmaxf(v, __shfl_xor_sync(0xffffffffu, v, 1));
                v = fmaxf(v, __shfl_xor_sync(0xffffffffu, v, 2));
                if (t == 0) {
                    const int row = m0 + wm * 32 + mt * 16 + h * 8 + g;
                    const int b = row / R;
                    const float denom = (float)obj_nums[b] + 1e-6f;
                    const int c = cbase + wn * CPW + cap;
                    atomicAdd(&g_scores[b * Bsz + c], __fdividef(v, denom));
                }
            }
}

__global__ void loss_kernel(int Bsz) {
    __shared__ float red[256];
    const int tid = threadIdx.x;
    const int n = Bsz * Bsz;
    float sum = 0.0f;
    for (int idx = blockIdx.x * blockDim.x + tid; idx < n; idx += gridDim.x * blockDim.x) {
        const int i = idx / Bsz;
        const int j = idx - i * Bsz;
        if (i != j) {
            const float sc = g_scores[idx];
            const float di = g_scores[i * Bsz + i];
            const float dj = g_scores[j * Bsz + j];
            sum += fmaxf(0.0f, 0.2f + sc - di);
            sum += fmaxf(0.0f, 0.2f + sc - dj);
        }
    }
    red[tid] = sum;
    __syncthreads();
    for (int s = 128; s > 0; s >>= 1) {
        if (tid < s) red[tid] += red[tid + s];
        __syncthreads();
    }
    if (tid == 0) atomicAdd(&g_loss, red[0]);
}

__global__ void write_out_kernel(float* out, int out_size, int n) {
    const int i = blockIdx.x * blockDim.x + threadIdx.x;
    if (i >= out_size) return;
    if (out_size == n) { out[i] = g_scores[i]; return; }
    if (out_size == 1) { out[0] = g_loss; return; }
    if (i == 0) { out[0] = g_loss; return; }
    const int j = i - 1;
    out[i] = (j < n) ? g_scores[j] : 0.0f;
}

extern "C" void kernel_launch(void* const* d_in, const int* in_sizes, int n_in,
                              void* d_out, int out_size) {
    const float* im   = (const float*)d_in[0];
    const int*   im_l = (const int*)  d_in[1];
    const float* s    = (const float*)d_in[2];
    const int*   s_l  = (const int*)  d_in[3];
    const float* pred = (const float*)d_in[4];
    const int*   pr_l = (const int*)  d_in[5];
    const float* sp   = (const float*)d_in[6];
    const int*   sp_l = (const int*)  d_in[7];

    const int Bsz = in_sizes[1];                 // 128
    const int R   = in_sizes[0] / (Bsz * D);     // 36
    const int W   = in_sizes[2] / (Bsz * D);     // 50
    const int Rp  = in_sizes[4] / (Bsz * D);     // 25
    const int Wp  = in_sizes[6] / (Bsz * D);     // 30

    __nv_bfloat16 *A1, *B1, *A2, *B2;
    cudaGetSymbolAddress((void**)&A1, g_A1);
    cudaGetSymbolAddress((void**)&B1, g_B1);
    cudaGetSymbolAddress((void**)&A2, g_A2);
    cudaGetSymbolAddress((void**)&B2, g_B2);

    static bool attr_set = false;
    if (!attr_set) {
        cudaFuncSetAttribute(xattn_cp_kernel<7, 56>, cudaFuncAttributeMaxDynamicSharedMemorySize, SMEM_DYN);
        cudaFuncSetAttribute(xattn_cp_kernel<8, 32>, cudaFuncAttributeMaxDynamicSharedMemorySize, SMEM_DYN);
        attr_set = true;
    }

    zero_kernel<<<(Bsz * Bsz + 255) / 256, 256>>>(Bsz * Bsz);

    // single conversion pre-pass for all four tensors
    cvt_all_kernel<<<(NCVT + 255) / 256, 256>>>(im, s, pred, sp);

    // part 1: W=50 -> pad 56; 1 caption/warp
    dim3 g1(M1 / BM, Bsz / 2);   // (36, 64)
    xattn_cp_kernel<7, 56><<<g1, 256, SMEM_DYN>>>(A1, B1, s_l, im_l, R, W, Bsz);
    // part 2: W=30 -> pad 32; 2 captions/warp
    dim3 g2(M2 / BM, Bsz / 4);   // (25, 32)
    xattn_cp_kernel<8, 32><<<g2, 256, SMEM_DYN>>>(A2, B2, sp_l, pr_l, Rp, Wp, Bsz);

    loss_kernel<<<32, 256>>>(Bsz);
    write_out_kernel<<<(out_size + 255) / 256, 256>>>((float*)d_out, out_size, Bsz * Bsz);
}

// round 15
// speedup vs baseline: 1.2510x; 1.2510x over previous
#include <cuda_runtime.h>
#include <cuda_bf16.h>
#include <cstdint>

// ============================================================================
// ContrastiveLoss via mma.sync bf16 m16n8k16 + ldmatrix + cp.async.
// Round 15: R14 with the alignment bug fixed — SROWB=144 (multiple of 16;
// 136 put odd rows at 8-mod-16 addresses -> misaligned ldmatrix/cp.async).
// BK=64 (16 chunks, half the barrier convoys), 3-stage ring, depth-1
// issue-before-wait (R11 pipeline), merged cvt pre-pass.
// scores[b,c] = sum_r max_{w<cl[c]} <A[b,r,:], S[c,w,:]> / (obj[b]+1e-6)
// ============================================================================

namespace {
constexpr int D = 1024;
constexpr int BM = 128;
constexpr int BK = 64;                  // k elems per chunk (4 x k16 steps)
constexpr int NCHUNK = D / BK;          // 16
constexpr int SROWB = 144;              // bytes per smem row (128 B data + 16 pad; mult of 16)
constexpr int STAGE_BYTES = BM * SROWB; // 18432
constexpr int SMEM_DYN = 6 * STAGE_BYTES;    // 110592 (A:0..2, B:3..5)
constexpr int BSZ_C = 128;
constexpr int R1 = 36, W1 = 50;
constexpr int R2 = 25, W2 = 30;
constexpr int M1 = BSZ_C * R1;          // 4608
constexpr int M2 = BSZ_C * R2;          // 3200
// cvt segment sizes in float4 units
constexpr int NA1 = M1 * D / 4;
constexpr int NB1 = BSZ_C * W1 * D / 4;
constexpr int NA2 = M2 * D / 4;
constexpr int NB2 = BSZ_C * W2 * D / 4;
constexpr int NCVT = NA1 + NB1 + NA2 + NB2;
}

__device__ __nv_bfloat16 g_A1[M1 * D];
__device__ __nv_bfloat16 g_B1[BSZ_C * W1 * D];
__device__ __nv_bfloat16 g_A2[M2 * D];
__device__ __nv_bfloat16 g_B2[BSZ_C * W2 * D];
__device__ float g_scores[BSZ_C * BSZ_C];
__device__ float g_loss;

__global__ void zero_kernel(int n) {
    int i = blockIdx.x * blockDim.x + threadIdx.x;
    if (i < n) g_scores[i] = 0.0f;
    if (i == 0) g_loss = 0.0f;
}

__device__ __forceinline__ uint32_t smem_u32(const void* p) {
    uint32_t a;
    asm("{ .reg .u64 t; cvta.to.shared.u64 t, %1; cvt.u32.u64 %0, t; }" : "=r"(a) : "l"(p));
    return a;
}
__device__ __forceinline__ uint32_t pack_bf16(float lo, float hi) {
    __nv_bfloat162 h = __floats2bfloat162_rn(lo, hi);
    return *reinterpret_cast<uint32_t*>(&h);
}
__device__ __forceinline__ void ldsm_x4(uint32_t addr, uint32_t* r) {
    asm volatile("ldmatrix.sync.aligned.m8n8.x4.shared.b16 {%0,%1,%2,%3}, [%4];"
                 : "=r"(r[0]), "=r"(r[1]), "=r"(r[2]), "=r"(r[3]) : "r"(addr));
}
__device__ __forceinline__ void ldsm_x2(uint32_t addr, uint32_t* r) {
    asm volatile("ldmatrix.sync.aligned.m8n8.x2.shared.b16 {%0,%1}, [%2];"
                 : "=r"(r[0]), "=r"(r[1]) : "r"(addr));
}
__device__ __forceinline__ void mma_bf16(float* c, const uint32_t* a, const uint32_t* b) {
    asm volatile(
        "mma.sync.aligned.m16n8k16.row.col.f32.bf16.bf16.f32 "
        "{%0,%1,%2,%3}, {%4,%5,%6,%7}, {%8,%9}, {%0,%1,%2,%3};"
        : "+f"(c[0]), "+f"(c[1]), "+f"(c[2]), "+f"(c[3])
        : "r"(a[0]), "r"(a[1]), "r"(a[2]), "r"(a[3]), "r"(b[0]), "r"(b[1]));
}
__device__ __forceinline__ void cp16(uint32_t dst, const void* src) {
    asm volatile("cp.async.cg.shared.global [%0], [%1], 16;" :: "r"(dst), "l"(src));
}

// single fp32->bf16 pre-pass covering all four tensors
__global__ void cvt_all_kernel(const float* __restrict__ im, const float* __restrict__ s,
                               const float* __restrict__ pred, const float* __restrict__ sp) {
    int i = blockIdx.x * blockDim.x + threadIdx.x;
    const float* src;
    __nv_bfloat16* dst;
    int j = i;
    if (j < NA1)                { src = im;   dst = g_A1; }
    else if ((j -= NA1) < NB1)  { src = s;    dst = g_B1; }
    else if ((j -= NB1) < NA2)  { src = pred; dst = g_A2; }
    else if ((j -= NA2) < NB2)  { src = sp;   dst = g_B2; }
    else return;
    float4 v = ((const float4*)src)[j];
    ((uint2*)dst)[j] = make_uint2(pack_bf16(v.x, v.y), pack_bf16(v.z, v.w));
}

// A: bf16 [Bsz*R, D]; Bm: bf16 [Bsz, W, D].
template <int NT, int WPAD>
__global__ void __launch_bounds__(256, 2)
xattn_cp_kernel(const __nv_bfloat16* __restrict__ A, const __nv_bfloat16* __restrict__ Bm,
                const int* __restrict__ cap_lens, const int* __restrict__ obj_nums,
                int R, int W, int Bsz)
{
    constexpr int BNW = NT * 8;              // cols per warp (56 or 64)
    constexpr int BN  = 2 * BNW;             // cols per CTA (112 or 128)
    constexpr int CPW = BNW / WPAD;          // captions per warp (1 or 2)
    constexpr int CAPS_PER_TILE = 2 * CPW;
    constexpr int NB4 = NT / 2;
    constexpr bool HASX2 = (NT & 1) != 0;

    extern __shared__ __align__(16) unsigned char smraw[];   // [6][STAGE_BYTES]
    const uint32_t sbase = smem_u32(smraw);

    const int tid  = threadIdx.x;
    const int wid  = tid >> 5;
    const int lane = tid & 31;
    const int g = lane >> 2;
    const int t = lane & 3;
    const int wm = wid & 3;
    const int wn = wid >> 2;
    const int m0 = blockIdx.x * BM;
    const int cbase = blockIdx.y * CAPS_PER_TILE;

    // ---- cp.async slot mapping: slot = tid + i*256 (i=0..3); row = slot/8; c16 = slot%8
    const __nv_bfloat16* srcA[4];
    const __nv_bfloat16* srcB[4];
    bool bval[4];
    uint32_t dstOff[4];
#pragma unroll
    for (int i = 0; i < 4; i++) {
        const int slot = tid + i * 256;
        const int row  = slot >> 3;          // 0..127
        const int c16  = slot & 7;           // 0..7 (16B units within 128B row)
        dstOff[i] = (uint32_t)(row * SROWB + c16 * 16);
        srcA[i] = A + (size_t)(m0 + row) * D + c16 * 8;
        const int cap  = row / WPAD;
        const int word = row - cap * WPAD;
        bval[i] = (row < BN) && (word < W);
        const int capc = (cap < CAPS_PER_TILE) ? cap : 0;
        srcB[i] = Bm + ((size_t)(cbase + capc) * W + word) * D + c16 * 8;
    }

    // zero B-stage rows cp.async never writes (padding words / row >= BN)
    {
        const uint4 z = make_uint4(0u, 0u, 0u, 0u);
        for (int idx = tid; idx < 128 * 8; idx += 256) {
            const int row = idx >> 3;
            const int c   = idx & 7;
            const int cap  = row / WPAD;
            const int word = row - cap * WPAD;
            const bool valid = (row < BN) && (word < W);
            if (!valid) {
#pragma unroll
                for (int s = 0; s < 3; s++)
                    *(uint4*)(smraw + (3 + s) * STAGE_BYTES + row * SROWB + c * 16) = z;
            }
        }
    }

    float acc[2][NT][4];
#pragma unroll
    for (int mt = 0; mt < 2; mt++)
#pragma unroll
        for (int nt = 0; nt < NT; nt++)
#pragma unroll
            for (int e = 0; e < 4; e++) acc[mt][nt][e] = 0.0f;

    uint32_t aoff[2];
#pragma unroll
    for (int mt = 0; mt < 2; mt++)
        aoff[mt] = (uint32_t)((wm * 32 + mt * 16 + (lane & 15)) * SROWB + ((lane >> 4) << 4));
    uint32_t boff[NB4 + (HASX2 ? 1 : 0)];
#pragma unroll
    for (int nb = 0; nb < NB4; nb++) {
        const int n_local = (lane & 7) + ((lane & 16) ? 8 : 0);
        const int kb = (lane & 8) ? 16 : 0;
        boff[nb] = (uint32_t)((wn * BNW + nb * 16 + n_local) * SROWB + kb);
    }
    if (HASX2) {
        const int n_local = lane & 7;
        const int kb = (lane & 8) ? 16 : 0;
        boff[NB4] = (uint32_t)((wn * BNW + NB4 * 16 + n_local) * SROWB + kb);
    }

    auto issue = [&](int ch) {
        const int s = ch % 3;
        const int off = ch * BK;     // bf16 elements
#pragma unroll
        for (int i = 0; i < 4; i++)
            cp16(sbase + s * STAGE_BYTES + dstOff[i], srcA[i] + off);
#pragma unroll
        for (int i = 0; i < 4; i++)
            if (bval[i])
                cp16(sbase + (3 + s) * STAGE_BYTES + dstOff[i], srcB[i] + off);
        asm volatile("cp.async.commit_group;" ::: "memory");
    };

    auto compute = [&](int s) {
        const uint32_t abase = sbase + s * STAGE_BYTES;
        const uint32_t bbase = sbase + (3 + s) * STAGE_BYTES;
#pragma unroll
        for (int ks = 0; ks < 4; ks++) {
            const uint32_t ko = ks * 32;     // 16 bf16 = 32 bytes
            uint32_t afr[2][4];
#pragma unroll
            for (int mt = 0; mt < 2; mt++) ldsm_x4(abase + aoff[mt] + ko, afr[mt]);
            uint32_t bfr[NB4 + (HASX2 ? 1 : 0)][4];
#pragma unroll
            for (int nb = 0; nb < NB4; nb++) ldsm_x4(bbase + boff[nb] + ko, bfr[nb]);
            if (HASX2) ldsm_x2(bbase + boff[NB4] + ko, bfr[NB4]);
#pragma unroll
            for (int mt = 0; mt < 2; mt++)
#pragma unroll
                for (int nt = 0; nt < NT; nt++)
                    mma_bf16(acc[mt][nt], afr[mt], &bfr[nt >> 1][(nt & 1) * 2]);
        }
    };

    // depth-1 prefetch, issue-before-wait (R11 pipeline)
    issue(0);

    for (int ch = 0; ch < NCHUNK; ch++) {
        if (ch + 1 < NCHUNK) {
            issue(ch + 1);
            asm volatile("cp.async.wait_group 1;" ::: "memory");   // stage ch ready
        } else {
            asm volatile("cp.async.wait_group 0;" ::: "memory");
        }
        __syncthreads();
        compute(ch % 3);
    }

    // ---- epilogue
    int clv[CPW];
#pragma unroll
    for (int cap = 0; cap < CPW; cap++)
        clv[cap] = cap_lens[cbase + wn * CPW + cap];

    float mx[2][2][CPW];
#pragma unroll
    for (int mt = 0; mt < 2; mt++)
#pragma unroll
        for (int h = 0; h < 2; h++)
#pragma unroll
            for (int cap = 0; cap < CPW; cap++)
                mx[mt][h][cap] = -1e30f;

#pragma unroll
    for (int mt = 0; mt < 2; mt++)
#pragma unroll
        for (int nt = 0; nt < NT; nt++)
#pragma unroll
            for (int e = 0; e < 2; e++) {
                const int wc = nt * 8 + 2 * t + e;
                const int cap  = wc / WPAD;
                const int wpos = wc - cap * WPAD;
                if (wpos < clv[cap]) {
                    mx[mt][0][cap] = fmaxf(mx[mt][0][cap], acc[mt][nt][e]);
                    mx[mt][1][cap] = fmaxf(mx[mt][1][cap], acc[mt][nt][2 + e]);
                }
            }

#pragma unroll
    for (int mt = 0; mt < 2; mt++)
#pragma unroll
        for (int h = 0; h < 2; h++)
#pragma unroll
            for (int cap = 0; cap < CPW; cap++) {
                float v = mx[mt][h][cap];
                v = fmaxf(v, __shfl_xor_sync(0xffffffffu, v, 1));
                v = fmaxf(v, __shfl_xor_sync(0xffffffffu, v, 2));
                if (t == 0) {
                    const int row = m0 + wm * 32 + mt * 16 + h * 8 + g;
                    const int b = row / R;
                    const float denom = (float)obj_nums[b] + 1e-6f;
                    const int c = cbase + wn * CPW + cap;
                    atomicAdd(&g_scores[b * Bsz + c], __fdividef(v, denom));
                }
            }
}

__global__ void loss_kernel(int Bsz) {
    __shared__ float red[256];
    const int tid = threadIdx.x;
    const int n = Bsz * Bsz;
    float sum = 0.0f;
    for (int idx = blockIdx.x * blockDim.x + tid; idx < n; idx += gridDim.x * blockDim.x) {
        const int i = idx / Bsz;
        const int j = idx - i * Bsz;
        if (i != j) {
            const float sc = g_scores[idx];
            const float di = g_scores[i * Bsz + i];
            const float dj = g_scores[j * Bsz + j];
            sum += fmaxf(0.0f, 0.2f + sc - di);
            sum += fmaxf(0.0f, 0.2f + sc - dj);
        }
    }
    red[tid] = sum;
    __syncthreads();
    for (int s = 128; s > 0; s >>= 1) {
        if (tid < s) red[tid] += red[tid + s];
        __syncthreads();
    }
    if (tid == 0) atomicAdd(&g_loss, red[0]);
}

__global__ void write_out_kernel(float* out, int out_size, int n) {
    const int i = blockIdx.x * blockDim.x + threadIdx.x;
    if (i >= out_size) return;
    if (out_size == n) { out[i] = g_scores[i]; return; }
    if (out_size == 1) { out[0] = g_loss; return; }
    if (i == 0) { out[0] = g_loss; return; }
    const int j = i - 1;
    out[i] = (j < n) ? g_scores[j] : 0.0f;
}

extern "C" void kernel_launch(void* const* d_in, const int* in_sizes, int n_in,
                              void* d_out, int out_size) {
    const float* im   = (const float*)d_in[0];
    const int*   im_l = (const int*)  d_in[1];
    const float* s    = (const float*)d_in[2];
    const int*   s_l  = (const int*)  d_in[3];
    const float* pred = (const float*)d_in[4];
    const int*   pr_l = (const int*)  d_in[5];
    const float* sp   = (const float*)d_in[6];
    const int*   sp_l = (const int*)  d_in[7];

    const int Bsz = in_sizes[1];                 // 128
    const int R   = in_sizes[0] / (Bsz * D);     // 36
    const int W   = in_sizes[2] / (Bsz * D);     // 50
    const int Rp  = in_sizes[4] / (Bsz * D);     // 25
    const int Wp  = in_sizes[6] / (Bsz * D);     // 30

    __nv_bfloat16 *A1, *B1, *A2, *B2;
    cudaGetSymbolAddress((void**)&A1, g_A1);
    cudaGetSymbolAddress((void**)&B1, g_B1);
    cudaGetSymbolAddress((void**)&A2, g_A2);
    cudaGetSymbolAddress((void**)&B2, g_B2);

    static bool attr_set = false;
    if (!attr_set) {
        cudaFuncSetAttribute(xattn_cp_kernel<7, 56>, cudaFuncAttributeMaxDynamicSharedMemorySize, SMEM_DYN);
        cudaFuncSetAttribute(xattn_cp_kernel<8, 32>, cudaFuncAttributeMaxDynamicSharedMemorySize, SMEM_DYN);
        attr_set = true;
    }

    zero_kernel<<<(Bsz * Bsz + 255) / 256, 256>>>(Bsz * Bsz);

    // single conversion pre-pass for all four tensors
    cvt_all_kernel<<<(NCVT + 255) / 256, 256>>>(im, s, pred, sp);

    // part 1: W=50 -> pad 56; 1 caption/warp
    dim3 g1(M1 / BM, Bsz / 2);   // (36, 64)
    xattn_cp_kernel<7, 56><<<g1, 256, SMEM_DYN>>>(A1, B1, s_l, im_l, R, W, Bsz);
    // part 2: W=30 -> pad 32; 2 captions/warp
    dim3 g2(M2 / BM, Bsz / 4);   // (25, 32)
    xattn_cp_kernel<8, 32><<<g2, 256, SMEM_DYN>>>(A2, B2, sp_l, pr_l, Rp, Wp, Bsz);

    loss_kernel<<<32, 256>>>(Bsz);
    write_out_kernel<<<(out_size + 255) / 256, 256>>>((float*)d_out, out_size, Bsz * Bsz);
}